// round 7
// baseline (speedup 1.0000x reference)
#include <cuda_runtime.h>

#define NEGV (-1e9f)

#define B_   32
#define N_   256
#define CIN  1024
#define CH   2048
#define ROWS (B_ * N_)          /* 8192 */

#define KT    16
#define STG   3
#define ASZ   (128 * KT)        /* floats per A stage  */
#define BSZ   (KT * 128)        /* floats per B stage  */
#define STAGE (ASZ + BSZ)       /* 4096 floats = 16 KB */
#define SMEMB (STG * STAGE * 4) /* 49152 B dynamic     */

/* ------------- scratch (device globals: the allowed alloc-free path) ---- */
__device__ float g_ax [ROWS * CH];
__device__ float g_ux [ROWS * CH];
__device__ float g_e1 [ROWS * CH];
__device__ float g_e2 [ROWS * CH];
__device__ float g_tb [ROWS * CH];
__device__ float g_m1 [ROWS * CH];
__device__ float g_m2 [ROWS * CH];
__device__ float g_e2t[ROWS * CH];
__device__ float g_cat[ROWS * 2 * CH];
__device__ float g_sb [B_ * N_ * N_];
__device__ float g_sbt[B_ * N_ * N_];
__device__ float g_col[2 * ROWS];

/* ------------- packed fp32x2 helpers (Blackwell FFMA2) ------------------ */
__device__ __forceinline__ unsigned long long pk2(float x, float y) {
    unsigned long long r;
    asm("mov.b64 %0, {%1,%2};" : "=l"(r) : "f"(x), "f"(y));
    return r;
}
__device__ __forceinline__ void upk2(unsigned long long v, float& x, float& y) {
    asm("mov.b64 {%0,%1}, %2;" : "=f"(x), "=f"(y) : "l"(v));
}
__device__ __forceinline__ void ffma2(unsigned long long& d, unsigned long long a,
                                      unsigned long long b) {
    asm("fma.rn.f32x2 %0, %1, %2, %0;" : "+l"(d) : "l"(a), "l"(b));
}
__device__ __forceinline__ void addf2(unsigned long long& d, unsigned long long a) {
    asm("add.rn.f32x2 %0, %0, %1;" : "+l"(d) : "l"(a));
}
__device__ __forceinline__ void cpasync16(unsigned saddr, const float* g) {
    asm volatile("cp.async.ca.shared.global [%0], [%1], 16;" :: "r"(saddr), "l"(g));
}

/* ------------- SGEMM: C = A * B (+bias)(relu)(*rowscale)(+addend)
 * A: (M x K) row-major; B: (K x N) row-major. All dims multiples of tile.
 * 128x128x16 tile, 256 threads, 8x8 micro-tile, f32x2 accumulators.
 * 3-stage cp.async pipeline (prefetch depth 2) hides global latency.
 * A smem [m][KT] row-major: a-values for 4 consecutive kk load as one
 * broadcast LDS.128 (2 wavefronts/kk vs 8 scalar). 8-wide columns halve the
 * pk2(a,a) MOV tax per FFMA2. kk order per accumulator and tacc per-tile
 * partial accumulation identical to prior rounds -> rel_err unchanged. */
template <bool RELU>
__global__ __launch_bounds__(256) void gemm_k(
    int M, int N, int K,
    const float* __restrict__ A, int lda, long long sA,
    const float* __restrict__ Bm, int ldb, long long sB,
    float* __restrict__ C, int ldc, long long sC,
    const float* __restrict__ bias,
    const float* __restrict__ rowscale,
    const float* __restrict__ addend, int ldadd, long long sAdd)
{
    extern __shared__ float sm[];
    const int bz = blockIdx.z;
    A  += (long long)bz * sA;
    Bm += (long long)bz * sB;
    C  += (long long)bz * sC;
    const int m0 = blockIdx.x * 128, n0 = blockIdx.y * 128;
    const int tid = threadIdx.x;
    const int tx = tid & 15, ty = tid >> 4;     /* 8x8 micro-tile */

    /* copy mapping: 2 float4 chunks each of A and B per thread per tile */
    const int ar = tid >> 2, ac = (tid & 3) << 2;    /* A rows ar, ar+64    */
    const int bk = tid >> 5, bc = (tid & 31) << 2;   /* B k-rows bk, bk+8   */
    const float* ag0 = A + (long long)(m0 + ar) * lda + ac;
    const float* ag1 = ag0 + 64LL * lda;
    const float* bg0 = Bm + (long long)bk * ldb + n0 + bc;
    const float* bg1 = bg0 + 8LL * ldb;
    const unsigned sbase = (unsigned)__cvta_generic_to_shared(sm);
    const unsigned as0 = sbase + (ar * KT + ac) * 4;
    const unsigned as1 = sbase + ((ar + 64) * KT + ac) * 4;
    const unsigned bs0 = sbase + (ASZ + bk * 128 + bc) * 4;
    const unsigned bs1 = sbase + (ASZ + (bk + 8) * 128 + bc) * 4;

    const int ntiles = K >> 4;

#define ISSUE(t, s) do {                                               \
        long long ko = (long long)(t) * KT;                            \
        cpasync16(as0 + (s) * (STAGE * 4), ag0 + ko);                  \
        cpasync16(as1 + (s) * (STAGE * 4), ag1 + ko);                  \
        cpasync16(bs0 + (s) * (STAGE * 4), bg0 + ko * ldb);            \
        cpasync16(bs1 + (s) * (STAGE * 4), bg1 + ko * ldb);            \
        asm volatile("cp.async.commit_group;");                        \
    } while (0)

    ISSUE(0, 0);
    ISSUE(1, 1);

    unsigned long long acc[8][4];
#pragma unroll
    for (int i = 0; i < 8; i++)
#pragma unroll
        for (int j = 0; j < 4; j++) acc[i][j] = 0ull;

    int s = 0;
    for (int t = 0; t < ntiles; ++t) {
        if (t + 1 < ntiles) asm volatile("cp.async.wait_group 1;");
        else                asm volatile("cp.async.wait_group 0;");
        __syncthreads();
        if (t + 2 < ntiles) {
            int s2 = s + 2; if (s2 >= STG) s2 -= STG;
            ISSUE(t + 2, s2);
        }
        const float* as = sm + s * STAGE + (ty << 3) * KT;
        const float* bs = sm + s * STAGE + ASZ;

        unsigned long long tacc[8][4];
#pragma unroll
        for (int i = 0; i < 8; i++)
#pragma unroll
            for (int j = 0; j < 4; j++) tacc[i][j] = 0ull;

#pragma unroll
        for (int k4 = 0; k4 < KT; k4 += 4) {
            float4 a4[8];
#pragma unroll
            for (int i = 0; i < 8; i++)
                a4[i] = *(const float4*)&as[i * KT + k4];   /* 4 kk at once */
#pragma unroll
            for (int u = 0; u < 4; u++) {
                const float* brow = &bs[(k4 + u) * 128 + (tx << 3)];
                float4 b0 = *(const float4*)brow;
                float4 b1 = *(const float4*)(brow + 4);
                unsigned long long bp[4] = { pk2(b0.x, b0.y), pk2(b0.z, b0.w),
                                             pk2(b1.x, b1.y), pk2(b1.z, b1.w) };
#pragma unroll
                for (int i = 0; i < 8; i++) {
                    float av = (&a4[i].x)[u];
                    unsigned long long ai = pk2(av, av);
                    ffma2(tacc[i][0], ai, bp[0]);
                    ffma2(tacc[i][1], ai, bp[1]);
                    ffma2(tacc[i][2], ai, bp[2]);
                    ffma2(tacc[i][3], ai, bp[3]);
                }
            }
        }
#pragma unroll
        for (int i = 0; i < 8; i++)
#pragma unroll
            for (int j = 0; j < 4; j++) addf2(acc[i][j], tacc[i][j]);
        __syncthreads();
        if (++s == STG) s = 0;
    }
#undef ISSUE

#pragma unroll
    for (int i = 0; i < 8; i++) {
        const int row  = m0 + (ty << 3) + i;
        const int colb = n0 + (tx << 3);
        float out[8];
#pragma unroll
        for (int j = 0; j < 4; j++) upk2(acc[i][j], out[2 * j], out[2 * j + 1]);
        if (bias) {
#pragma unroll
            for (int j = 0; j < 8; j++) out[j] += bias[colb + j];
        }
        if (RELU) {
#pragma unroll
            for (int j = 0; j < 8; j++) out[j] = fmaxf(out[j], 0.f);
        }
        if (rowscale) {
            float rs = rowscale[row];
#pragma unroll
            for (int j = 0; j < 8; j++) out[j] *= rs;
        }
        if (addend) {
            const float* adp = addend + (long long)bz * sAdd + (long long)row * ldadd + colb;
#pragma unroll
            for (int j = 0; j < 8; j++) out[j] += adp[j];
        }
        float* cp = C + (long long)row * ldc + colb;
        *(float4*)cp       = make_float4(out[0], out[1], out[2], out[3]);
        *(float4*)(cp + 4) = make_float4(out[4], out[5], out[6], out[7]);
    }
}

/* ------------- batched transpose: out[b][c][r] = in[b][r][c] ------------ */
__global__ void transpose_kernel(const float* __restrict__ in, float* __restrict__ out,
                                 int R, int C)
{
    __shared__ float tile[32][33];
    const long long boff = (long long)blockIdx.z * R * C;
    int x  = blockIdx.x * 32 + threadIdx.x;
    int y0 = blockIdx.y * 32 + threadIdx.y;
#pragma unroll
    for (int j = 0; j < 32; j += 8)
        tile[threadIdx.y + j][threadIdx.x] = in[boff + (long long)(y0 + j) * C + x];
    __syncthreads();
    int xo = blockIdx.y * 32 + threadIdx.x;
    int yo = blockIdx.x * 32 + threadIdx.y;
#pragma unroll
    for (int j = 0; j < 32; j += 8)
        out[boff + (long long)(yo + j) * R + xo] = tile[threadIdx.x][threadIdx.y + j];
}

/* ------------- inverse column-L1 norms of A: inv[b*256+m] = 1/max(sum_n|A|,1e-12) */
__global__ void colnorm_kernel(const float* __restrict__ A, float* __restrict__ inv)
{
    int g = blockIdx.x * blockDim.x + threadIdx.x;   /* 0..8191 */
    int b = g >> 8, m = g & 255;
    const float* base = A + (long long)b * 65536 + m;
    float s = 0.f;
#pragma unroll 8
    for (int n = 0; n < 256; n++) s += fabsf(base[n * 256]);
    inv[g] = 1.f / fmaxf(s, 1e-12f);
}

/* ------------- copy (8192 x 2048) into left half of (8192 x 4096) ------- */
__global__ void copycat_kernel(const float* __restrict__ src, float* __restrict__ dst)
{
    long long i = (long long)blockIdx.x * blockDim.x + threadIdx.x;  /* float4 idx */
    long long row = i >> 9;          /* / 512 */
    long long c4  = i & 511;
    ((float4*)dst)[(row << 10) + c4] = ((const float4*)src)[i];
}

/* ------------- masked Sinkhorn, one CTA per batch, data in global/L2 ---- */
__global__ __launch_bounds__(1024) void sinkhorn_kernel(
    float* __restrict__ buf, float* __restrict__ out,
    const int* __restrict__ n1, const int* __restrict__ iters_ptr)
{
    __shared__ float red[4 * 256];
    __shared__ float lsebuf[256];
    const int b = blockIdx.x;
    float* Mb = buf + (long long)b * 65536;
    const int nv = n1[b];
    const int iters = *iters_ptr;
    const int tid = threadIdx.x;
    const int warp = tid >> 5, lane = tid & 31;

    for (int idx = tid; idx < 65536; idx += 1024) {
        int r = idx >> 8;
        float v = Mb[idx];
        Mb[idx] = (r < nv) ? v / 0.05f : NEGV;
    }
    __syncthreads();

    for (int it = 0; it < iters; ++it) {
        if ((it & 1) == 0) {
            for (int r = warp; r < 256; r += 32) {
                float* rp = Mb + (r << 8);
                float v[8];
#pragma unroll
                for (int j = 0; j < 8; j++) v[j] = rp[lane + (j << 5)];
                float mx = v[0];
#pragma unroll
                for (int j = 1; j < 8; j++) mx = fmaxf(mx, v[j]);
#pragma unroll
                for (int o = 16; o > 0; o >>= 1)
                    mx = fmaxf(mx, __shfl_xor_sync(0xffffffffu, mx, o));
                float sm = 0.f;
#pragma unroll
                for (int j = 0; j < 8; j++) sm += expf(v[j] - mx);
#pragma unroll
                for (int o = 16; o > 0; o >>= 1)
                    sm += __shfl_xor_sync(0xffffffffu, sm, o);
                float lse = mx + logf(sm);
                bool ok = r < nv;
#pragma unroll
                for (int j = 0; j < 8; j++)
                    rp[lane + (j << 5)] = ok ? (v[j] - lse) : NEGV;
            }
            __syncthreads();
        } else {
            const int c = tid & 255, g = tid >> 8;
            float pm = NEGV;
            for (int r = g; r < 256; r += 4) pm = fmaxf(pm, Mb[(r << 8) + c]);
            red[(g << 8) + c] = pm;
            __syncthreads();
            if (tid < 256) {
                float cm = fmaxf(fmaxf(red[tid], red[256 + tid]),
                                 fmaxf(red[512 + tid], red[768 + tid]));
                lsebuf[tid] = cm;
            }
            __syncthreads();
            float cm = lsebuf[c];
            float ps = 0.f;
            for (int r = g; r < 256; r += 4) ps += expf(Mb[(r << 8) + c] - cm);
            red[(g << 8) + c] = ps;
            __syncthreads();
            if (tid < 256) {
                float s4 = red[tid] + red[256 + tid] + red[512 + tid] + red[768 + tid];
                lsebuf[tid] = lsebuf[tid] + logf(s4);
            }
            __syncthreads();
            for (int idx = tid; idx < 65536; idx += 1024) {
                int r = idx >> 8, cc = idx & 255;
                Mb[idx] = (r < nv) ? (Mb[idx] - lsebuf[cc]) : NEGV;
            }
            __syncthreads();
        }
    }
    float* ob = out + (long long)b * 65536;
    for (int idx = tid; idx < 65536; idx += 1024)
        ob[idx] = expf(Mb[idx]);
}

/* ------------- orchestration -------------------------------------------- */
extern "C" void kernel_launch(void* const* d_in, const int* in_sizes, int n_in,
                              void* d_out, int out_size)
{
    (void)in_sizes; (void)n_in; (void)out_size;
    const float* feat1 = (const float*)d_in[0];
    const float* feat2 = (const float*)d_in[1];
    const float* A1p   = (const float*)d_in[2];
    const float* A2p   = (const float*)d_in[3];
    const int*   n1p   = (const int*)d_in[4];
    const int*   skp   = (const int*)d_in[7];
    const float* W0a = (const float*)d_in[8],  *b0a = (const float*)d_in[9];
    const float* W0u = (const float*)d_in[10], *b0u = (const float*)d_in[11];
    const float* W1a = (const float*)d_in[12], *b1a = (const float*)d_in[13];
    const float* W1u = (const float*)d_in[14], *b1u = (const float*)d_in[15];
    const float* Wc  = (const float*)d_in[16], *bc  = (const float*)d_in[17];
    const float* Aaff0 = (const float*)d_in[18];
    const float* Aaff1 = (const float*)d_in[19];
    float* outp = (float*)d_out;

    float *ax, *ux, *e1, *e2, *tb, *m1, *m2, *e2t, *cat, *sb, *sbt, *col;
    cudaGetSymbolAddress((void**)&ax,  g_ax);
    cudaGetSymbolAddress((void**)&ux,  g_ux);
    cudaGetSymbolAddress((void**)&e1,  g_e1);
    cudaGetSymbolAddress((void**)&e2,  g_e2);
    cudaGetSymbolAddress((void**)&tb,  g_tb);
    cudaGetSymbolAddress((void**)&m1,  g_m1);
    cudaGetSymbolAddress((void**)&m2,  g_m2);
    cudaGetSymbolAddress((void**)&e2t, g_e2t);
    cudaGetSymbolAddress((void**)&cat, g_cat);
    cudaGetSymbolAddress((void**)&sb,  g_sb);
    cudaGetSymbolAddress((void**)&sbt, g_sbt);
    cudaGetSymbolAddress((void**)&col, g_col);

    cudaFuncSetAttribute(gemm_k<true >, cudaFuncAttributeMaxDynamicSharedMemorySize, SMEMB);
    cudaFuncSetAttribute(gemm_k<false>, cudaFuncAttributeMaxDynamicSharedMemorySize, SMEMB);

    const dim3 blk(256);
    const dim3 tblk(32, 8);
    const long long SE = 256LL * 2048;
    const long long SS = 65536LL;
    const long long SCAT = 256LL * 4096;

    colnorm_kernel<<<32, 256>>>(A1p, col);
    colnorm_kernel<<<32, 256>>>(A2p, col + ROWS);

    /* ---- gconv layer 0 ---- */
    gemm_k<true ><<<dim3(64,16,1), blk, SMEMB>>>(8192,2048,1024, feat1,1024,0, W0a,2048,0, ax,2048,0, b0a, col,      nullptr,0,0);
    gemm_k<true ><<<dim3(64,16,1), blk, SMEMB>>>(8192,2048,1024, feat1,1024,0, W0u,2048,0, ux,2048,0, b0u, nullptr,  nullptr,0,0);
    gemm_k<false><<<dim3(2,16,32), blk, SMEMB>>>(256,2048,256, A1p,256,SS, ax,2048,SE, e1,2048,SE, nullptr,nullptr, ux,2048,SE);
    gemm_k<true ><<<dim3(64,16,1), blk, SMEMB>>>(8192,2048,1024, feat2,1024,0, W0a,2048,0, ax,2048,0, b0a, col+ROWS, nullptr,0,0);
    gemm_k<true ><<<dim3(64,16,1), blk, SMEMB>>>(8192,2048,1024, feat2,1024,0, W0u,2048,0, ux,2048,0, b0u, nullptr,  nullptr,0,0);
    gemm_k<false><<<dim3(2,16,32), blk, SMEMB>>>(256,2048,256, A2p,256,SS, ax,2048,SE, e2,2048,SE, nullptr,nullptr, ux,2048,SE);

    /* ---- affinity 0: s = (e1 @ Aaff0) @ e2^T  (via e2 transpose) ---- */
    gemm_k<false><<<dim3(64,16,1), blk, SMEMB>>>(8192,2048,2048, e1,2048,0, Aaff0,2048,0, tb,2048,0, nullptr,nullptr,nullptr,0,0);
    transpose_kernel<<<dim3(64,8,32), tblk>>>(e2, e2t, 256, 2048);
    gemm_k<false><<<dim3(2,2,32),  blk, SMEMB>>>(256,256,2048, tb,2048,SE, e2t,256,SE, sb,256,SS, nullptr,nullptr,nullptr,0,0);
    sinkhorn_kernel<<<32, 1024>>>(sb, sb, n1p, skp);

    /* ---- cross update ---- */
    copycat_kernel<<<16384, 256>>>(e1, cat);
    gemm_k<false><<<dim3(2,16,32), blk, SMEMB>>>(256,2048,256, sb,256,SS, e2,2048,SE, cat+2048,4096,SCAT, nullptr,nullptr,nullptr,0,0);
    gemm_k<false><<<dim3(64,16,1), blk, SMEMB>>>(8192,2048,4096, cat,4096,0, Wc,2048,0, m1,2048,0, bc, nullptr, nullptr,0,0);
    copycat_kernel<<<16384, 256>>>(e2, cat);
    transpose_kernel<<<dim3(8,8,32), tblk>>>(sb, sbt, 256, 256);
    gemm_k<false><<<dim3(2,16,32), blk, SMEMB>>>(256,2048,256, sbt,256,SS, e1,2048,SE, cat+2048,4096,SCAT, nullptr,nullptr,nullptr,0,0);
    gemm_k<false><<<dim3(64,16,1), blk, SMEMB>>>(8192,2048,4096, cat,4096,0, Wc,2048,0, m2,2048,0, bc, nullptr, nullptr,0,0);

    /* ---- gconv layer 1 ---- */
    gemm_k<true ><<<dim3(64,16,1), blk, SMEMB>>>(8192,2048,2048, m1,2048,0, W1a,2048,0, ax,2048,0, b1a, col,      nullptr,0,0);
    gemm_k<true ><<<dim3(64,16,1), blk, SMEMB>>>(8192,2048,2048, m1,2048,0, W1u,2048,0, ux,2048,0, b1u, nullptr,  nullptr,0,0);
    gemm_k<false><<<dim3(2,16,32), blk, SMEMB>>>(256,2048,256, A1p,256,SS, ax,2048,SE, e1,2048,SE, nullptr,nullptr, ux,2048,SE);
    gemm_k<true ><<<dim3(64,16,1), blk, SMEMB>>>(8192,2048,2048, m2,2048,0, W1a,2048,0, ax,2048,0, b1a, col+ROWS, nullptr,0,0);
    gemm_k<true ><<<dim3(64,16,1), blk, SMEMB>>>(8192,2048,2048, m2,2048,0, W1u,2048,0, ux,2048,0, b1u, nullptr,  nullptr,0,0);
    gemm_k<false><<<dim3(2,16,32), blk, SMEMB>>>(256,2048,256, A2p,256,SS, ax,2048,SE, e2,2048,SE, nullptr,nullptr, ux,2048,SE);

    /* ---- affinity 1 + final sinkhorn -> output ---- */
    gemm_k<false><<<dim3(64,16,1), blk, SMEMB>>>(8192,2048,2048, e1,2048,0, Aaff1,2048,0, tb,2048,0, nullptr,nullptr,nullptr,0,0);
    transpose_kernel<<<dim3(64,8,32), tblk>>>(e2, e2t, 256, 2048);
    gemm_k<false><<<dim3(2,2,32),  blk, SMEMB>>>(256,256,2048, tb,2048,SE, e2t,256,SE, sb,256,SS, nullptr,nullptr,nullptr,0,0);
    sinkhorn_kernel<<<32, 1024>>>(sb, outp, n1p, skp);
}

// round 9
// speedup vs baseline: 1.0548x; 1.0548x over previous
#include <cuda_runtime.h>
#include <cuda_bf16.h>

#define NEGV (-1e9f)
#define B_   32
#define N_   256
#define CH   2048
#define ROWS (B_ * N_)                 /* 8192 */
#define KT   16

/* plane strides (elements) */
#define PFEAT 8388608LL                /* 8192x1024 */
#define PW0   2097152LL                /* 1024x2048 tr-> 2048x1024 */
#define PADJ  2097152LL                /* 32x256x256 */
#define PBIG  16777216LL               /* 8192x2048 class */
#define PAAF  4194304LL                /* 2048x2048 */
#define PWC   8388608LL                /* 2048x4096 (Wc tr) */
#define PSB   2097152LL                /* 32x256x256 */

/* smem geometry: padded rows 24 bf16 = 48 B; 6 plane-tiles per stage */
#define APAD_B  48
#define ATILE_B (128 * APAD_B)         /* 6144 B */
#define STG_B   (6 * ATILE_B)          /* 36864 B */
#define NSTG    3
#define SMEMT   (NSTG * STG_B)         /* 110592 B */

/* ------------- scratch (device globals) --------------------------------- */
__device__ __nv_bfloat16 g_bfA [3LL * 8192 * 2048];
__device__ __nv_bfloat16 g_bfB [3LL * 8192 * 2048];
__device__ __nv_bfloat16 g_bfB2[3LL * 8192 * 2048];
__device__ float g_ax[ROWS * CH];
__device__ float g_ux[ROWS * CH];
__device__ float g_e1[ROWS * CH];
__device__ float g_e2[ROWS * CH];
__device__ float g_tb[ROWS * CH];
__device__ float g_m1[ROWS * CH];
__device__ float g_m2[ROWS * CH];
__device__ float g_sb[B_ * N_ * N_];
__device__ float g_col[2 * ROWS];

/* ------------- low-level helpers ---------------------------------------- */
__device__ __forceinline__ void cpasync16(unsigned saddr, const void* g) {
    asm volatile("cp.async.ca.shared.global [%0], [%1], 16;" :: "r"(saddr), "l"(g));
}
#define LDSM4(r, addr) \
    asm volatile("ldmatrix.sync.aligned.m8n8.x4.shared.b16 {%0,%1,%2,%3}, [%4];" \
        : "=r"((r)[0]), "=r"((r)[1]), "=r"((r)[2]), "=r"((r)[3]) : "r"(addr))
#define MMA(d, a, b0v, b1v) \
    asm volatile("mma.sync.aligned.m16n8k16.row.col.f32.bf16.bf16.f32 " \
        "{%0,%1,%2,%3},{%4,%5,%6,%7},{%8,%9},{%0,%1,%2,%3};" \
        : "+f"((d)[0]), "+f"((d)[1]), "+f"((d)[2]), "+f"((d)[3]) \
        : "r"((a)[0]), "r"((a)[1]), "r"((a)[2]), "r"((a)[3]), "r"(b0v), "r"(b1v))

/* ------------- tensor GEMM: C = A @ Bop^T, bf16x3 split, 6 products.
 * A planes: [M][lda] bf16 x3 (plane stride aPS); Bop planes: [N][ldb] x3.
 * CTA tile 128x128, 8 warps (warp tile 32x64), K-step 16, 3-stage cp.async.
 * a0*b0 -> cm (dominant, clean fp32 chain); 5 corrections -> cc.           */
__global__ __launch_bounds__(256) void tgemm(
    int M, int N, int K,
    const __nv_bfloat16* __restrict__ A, int lda, long long aPS, long long sAb,
    const __nv_bfloat16* __restrict__ B, int ldb, long long bPS, long long sBb,
    float* __restrict__ C, int ldc, long long sCb,
    const float* __restrict__ bias, int relu,
    const float* __restrict__ rowscale,
    const float* __restrict__ addend, int ldadd, long long sAddb)
{
    extern __shared__ unsigned char smem[];
    const int bz = blockIdx.z;
    A += (long long)bz * sAb;
    B += (long long)bz * sBb;
    C += (long long)bz * sCb;
    if (addend) addend += (long long)bz * sAddb;
    const int m0 = blockIdx.x * 128, n0 = blockIdx.y * 128;
    const int tid = threadIdx.x, lane = tid & 31, wid = tid >> 5;
    const unsigned sb = (unsigned)__cvta_generic_to_shared(smem);

    /* cp.async mapping: thread -> (row, 16B chunk) for both A and B tiles */
    const int cr = tid >> 1, ck = tid & 1;
    const __nv_bfloat16* aG = A + (long long)(m0 + cr) * lda + ck * 8;
    const __nv_bfloat16* bG = B + (long long)(n0 + cr) * ldb + ck * 8;
    const unsigned aS = sb + cr * APAD_B + ck * 16;
    const unsigned bS = sb + 3 * ATILE_B + cr * APAD_B + ck * 16;

    const int nst = K >> 4;
#define TISSUE(t, st) do {                                                \
        long long ko = (long long)(t) * KT;                               \
        _Pragma("unroll")                                                 \
        for (int p = 0; p < 3; p++) {                                     \
            cpasync16(aS + (st) * STG_B + p * ATILE_B, aG + p * aPS + ko);\
            cpasync16(bS + (st) * STG_B + p * ATILE_B, bG + p * bPS + ko);\
        }                                                                 \
        asm volatile("cp.async.commit_group;");                           \
    } while (0)

    TISSUE(0, 0);
    if (nst > 1) TISSUE(1, 1);

    float cm[2][8][4], cc[2][8][4];
#pragma unroll
    for (int i = 0; i < 2; i++)
#pragma unroll
        for (int j = 0; j < 8; j++)
#pragma unroll
            for (int k = 0; k < 4; k++) { cm[i][j][k] = 0.f; cc[i][j][k] = 0.f; }

    const int mw = (wid & 3) * 32, nw = (wid >> 2) * 64;
    const int q = lane >> 3, rl = lane & 7;
    const unsigned aoff = (mw + rl + (q & 1) * 8) * APAD_B + (q >> 1) * 16;
    const unsigned boff = 3 * ATILE_B + (nw + rl + (q & 1) * 8) * APAD_B + (q >> 1) * 16;

    int st = 0;
    for (int t = 0; t < nst; ++t) {
        if (t + 1 < nst) asm volatile("cp.async.wait_group 1;");
        else             asm volatile("cp.async.wait_group 0;");
        __syncthreads();
        if (t + 2 < nst) {
            int s2 = st + 2; if (s2 >= NSTG) s2 -= NSTG;
            TISSUE(t + 2, s2);
        }
        const unsigned sa = sb + st * STG_B + aoff;
        const unsigned sB2 = sb + st * STG_B + boff;

        unsigned a[3][2][4];
#pragma unroll
        for (int p = 0; p < 3; p++)
#pragma unroll
            for (int mi = 0; mi < 2; mi++)
                LDSM4(a[p][mi], sa + p * ATILE_B + mi * 16 * APAD_B);

#pragma unroll
        for (int ng = 0; ng < 4; ng++) {
            unsigned bf[3][4];
#pragma unroll
            for (int p = 0; p < 3; p++)
                LDSM4(bf[p], sB2 + p * ATILE_B + ng * 16 * APAD_B);
#pragma unroll
            for (int mi = 0; mi < 2; mi++)
#pragma unroll
                for (int j = 0; j < 2; j++) {
                    float* dm = cm[mi][ng * 2 + j];
                    float* dc = cc[mi][ng * 2 + j];
                    MMA(dm, a[0][mi], bf[0][j], bf[0][j + 2]);
                    MMA(dc, a[0][mi], bf[1][j], bf[1][j + 2]);
                    MMA(dc, a[1][mi], bf[0][j], bf[0][j + 2]);
                    MMA(dc, a[1][mi], bf[1][j], bf[1][j + 2]);
                    MMA(dc, a[0][mi], bf[2][j], bf[2][j + 2]);
                    MMA(dc, a[2][mi], bf[0][j], bf[0][j + 2]);
                }
        }
        __syncthreads();
        if (++st == NSTG) st = 0;
    }
#undef TISSUE

    /* epilogue: c-frag (mi): rows g/g+8, cols tg*2, tg*2+1 */
    const int g = lane >> 2, tg = lane & 3;
#pragma unroll
    for (int mi = 0; mi < 2; mi++) {
        const int r0 = m0 + mw + mi * 16 + g;
        const int r1 = r0 + 8;
        const float rs0 = rowscale ? rowscale[r0] : 1.f;
        const float rs1 = rowscale ? rowscale[r1] : 1.f;
#pragma unroll
        for (int nf = 0; nf < 8; nf++) {
            const int col = n0 + nw + nf * 8 + tg * 2;
            float o0 = cm[mi][nf][0] + cc[mi][nf][0];
            float o1 = cm[mi][nf][1] + cc[mi][nf][1];
            float o2 = cm[mi][nf][2] + cc[mi][nf][2];
            float o3 = cm[mi][nf][3] + cc[mi][nf][3];
            if (bias) {
                float bv0 = bias[col], bv1 = bias[col + 1];
                o0 += bv0; o1 += bv1; o2 += bv0; o3 += bv1;
            }
            if (relu) {
                o0 = fmaxf(o0, 0.f); o1 = fmaxf(o1, 0.f);
                o2 = fmaxf(o2, 0.f); o3 = fmaxf(o3, 0.f);
            }
            o0 *= rs0; o1 *= rs0; o2 *= rs1; o3 *= rs1;
            if (addend) {
                o0 += addend[(long long)r0 * ldadd + col];
                o1 += addend[(long long)r0 * ldadd + col + 1];
                o2 += addend[(long long)r1 * ldadd + col];
                o3 += addend[(long long)r1 * ldadd + col + 1];
            }
            *(float2*)(C + (long long)r0 * ldc + col) = make_float2(o0, o1);
            *(float2*)(C + (long long)r1 * ldc + col) = make_float2(o2, o3);
        }
    }
}

/* ------------- fp32 -> 3 bf16 planes ------------------------------------ */
__device__ __forceinline__ void split3(float v, __nv_bfloat16& b0,
                                       __nv_bfloat16& b1, __nv_bfloat16& b2) {
    b0 = __float2bfloat16(v);
    float r = v - __bfloat162float(b0);
    b1 = __float2bfloat16(r);
    float r2 = r - __bfloat162float(b1);
    b2 = __float2bfloat16(r2);
}
__global__ void split_rm(const float* __restrict__ in, __nv_bfloat16* __restrict__ out,
                         long long n, long long PS)
{
    long long i = (long long)blockIdx.x * blockDim.x + threadIdx.x;
    if (i >= n) return;
    __nv_bfloat16 b0, b1, b2;
    split3(in[i], b0, b1, b2);
    out[i] = b0; out[PS + i] = b1; out[2 * PS + i] = b2;
}
/* transpose + split: in [z][R][C] fp32 -> planes [z][C][R] bf16 */
__global__ void split_tr(const float* __restrict__ in, __nv_bfloat16* __restrict__ out,
                         int R, int C, long long PS)
{
    __shared__ float t[32][33];
    const long long zo = (long long)blockIdx.z * R * C;
    const float* ip = in + zo;
    __nv_bfloat16* op = out + zo;
    int x = blockIdx.x * 32 + threadIdx.x;
    int y0 = blockIdx.y * 32 + threadIdx.y;
#pragma unroll
    for (int j = 0; j < 32; j += 8)
        t[threadIdx.y + j][threadIdx.x] = ip[(long long)(y0 + j) * C + x];
    __syncthreads();
    int xo = blockIdx.y * 32 + threadIdx.x;
    int yo = blockIdx.x * 32 + threadIdx.y;
#pragma unroll
    for (int j = 0; j < 32; j += 8) {
        __nv_bfloat16 b0, b1, b2;
        split3(t[threadIdx.x][threadIdx.y + j], b0, b1, b2);
        long long oi = (long long)(yo + j) * R + xo;
        op[oi] = b0; op[PS + oi] = b1; op[2 * PS + oi] = b2;
    }
}

/* ------------- colnorm --------------------------------------------------- */
__global__ void colnorm_kernel(const float* __restrict__ A, float* __restrict__ inv)
{
    int g = blockIdx.x * blockDim.x + threadIdx.x;
    int b = g >> 8, m = g & 255;
    const float* base = A + (long long)b * 65536 + m;
    float s = 0.f;
#pragma unroll 8
    for (int n = 0; n < 256; n++) s += fabsf(base[n * 256]);
    inv[g] = 1.f / fmaxf(s, 1e-12f);
}

/* ------------- masked Sinkhorn ------------------------------------------- */
__global__ __launch_bounds__(1024) void sinkhorn_kernel(
    float* __restrict__ buf, float* __restrict__ out,
    const int* __restrict__ n1, const int* __restrict__ iters_ptr)
{
    __shared__ float red[4 * 256];
    __shared__ float lsebuf[256];
    const int b = blockIdx.x;
    float* Mb = buf + (long long)b * 65536;
    const int nv = n1[b];
    const int iters = *iters_ptr;
    const int tid = threadIdx.x;
    const int warp = tid >> 5, lane = tid & 31;

    for (int idx = tid; idx < 65536; idx += 1024) {
        int r = idx >> 8;
        float v = Mb[idx];
        Mb[idx] = (r < nv) ? v / 0.05f : NEGV;
    }
    __syncthreads();
    for (int it = 0; it < iters; ++it) {
        if ((it & 1) == 0) {
            for (int r = warp; r < 256; r += 32) {
                float* rp = Mb + (r << 8);
                float v[8];
#pragma unroll
                for (int j = 0; j < 8; j++) v[j] = rp[lane + (j << 5)];
                float mx = v[0];
#pragma unroll
                for (int j = 1; j < 8; j++) mx = fmaxf(mx, v[j]);
#pragma unroll
                for (int o = 16; o > 0; o >>= 1)
                    mx = fmaxf(mx, __shfl_xor_sync(0xffffffffu, mx, o));
                float sm = 0.f;
#pragma unroll
                for (int j = 0; j < 8; j++) sm += expf(v[j] - mx);
#pragma unroll
                for (int o = 16; o > 0; o >>= 1)
                    sm += __shfl_xor_sync(0xffffffffu, sm, o);
                float lse = mx + logf(sm);
                bool ok = r < nv;
#pragma unroll
                for (int j = 0; j < 8; j++)
                    rp[lane + (j << 5)] = ok ? (v[j] - lse) : NEGV;
            }
            __syncthreads();
        } else {
            const int c = tid & 255, g = tid >> 8;
            float pm = NEGV;
            for (int r = g; r < 256; r += 4) pm = fmaxf(pm, Mb[(r << 8) + c]);
            red[(g << 8) + c] = pm;
            __syncthreads();
            if (tid < 256)
                lsebuf[tid] = fmaxf(fmaxf(red[tid], red[256 + tid]),
                                    fmaxf(red[512 + tid], red[768 + tid]));
            __syncthreads();
            float cm = lsebuf[c];
            float ps = 0.f;
            for (int r = g; r < 256; r += 4) ps += expf(Mb[(r << 8) + c] - cm);
            red[(g << 8) + c] = ps;
            __syncthreads();
            if (tid < 256)
                lsebuf[tid] = lsebuf[tid] + logf(red[tid] + red[256 + tid] +
                                                 red[512 + tid] + red[768 + tid]);
            __syncthreads();
            for (int idx = tid; idx < 65536; idx += 1024) {
                int r = idx >> 8, cc2 = idx & 255;
                Mb[idx] = (r < nv) ? (Mb[idx] - lsebuf[cc2]) : NEGV;
            }
            __syncthreads();
        }
    }
    float* ob = out + (long long)b * 65536;
    for (int idx = tid; idx < 65536; idx += 1024)
        ob[idx] = expf(Mb[idx]);
}

/* ------------- orchestration -------------------------------------------- */
extern "C" void kernel_launch(void* const* d_in, const int* in_sizes, int n_in,
                              void* d_out, int out_size)
{
    (void)in_sizes; (void)n_in; (void)out_size;
    const float* feat1 = (const float*)d_in[0];
    const float* feat2 = (const float*)d_in[1];
    const float* A1p   = (const float*)d_in[2];
    const float* A2p   = (const float*)d_in[3];
    const int*   n1p   = (const int*)d_in[4];
    const int*   skp   = (const int*)d_in[7];
    const float* W0a = (const float*)d_in[8],  *b0a = (const float*)d_in[9];
    const float* W0u = (const float*)d_in[10], *b0u = (const float*)d_in[11];
    const float* W1a = (const float*)d_in[12], *b1a = (const float*)d_in[13];
    const float* W1u = (const float*)d_in[14], *b1u = (const float*)d_in[15];
    const float* Wc  = (const float*)d_in[16], *bc  = (const float*)d_in[17];
    const float* Aaff0 = (const float*)d_in[18];
    const float* Aaff1 = (const float*)d_in[19];
    float* outp = (float*)d_out;

    __nv_bfloat16 *bfA, *bfB, *bfB2;
    float *ax, *ux, *e1, *e2, *tb, *m1, *m2, *sb, *col;
    cudaGetSymbolAddress((void**)&bfA,  g_bfA);
    cudaGetSymbolAddress((void**)&bfB,  g_bfB);
    cudaGetSymbolAddress((void**)&bfB2, g_bfB2);
    cudaGetSymbolAddress((void**)&ax,  g_ax);
    cudaGetSymbolAddress((void**)&ux,  g_ux);
    cudaGetSymbolAddress((void**)&e1,  g_e1);
    cudaGetSymbolAddress((void**)&e2,  g_e2);
    cudaGetSymbolAddress((void**)&tb,  g_tb);
    cudaGetSymbolAddress((void**)&m1,  g_m1);
    cudaGetSymbolAddress((void**)&m2,  g_m2);
    cudaGetSymbolAddress((void**)&sb,  g_sb);
    cudaGetSymbolAddress((void**)&col, g_col);

    cudaFuncSetAttribute(tgemm, cudaFuncAttributeMaxDynamicSharedMemorySize, SMEMT);

    const dim3 T32(32, 8);
    const long long SE = 524288;            /* 256*2048 per-batch */
    const long long SS = 65536;

    colnorm_kernel<<<32, 256>>>(A1p, col);
    colnorm_kernel<<<32, 256>>>(A2p, col + ROWS);

    /* gconv layer 0 : graph g = 1,2 */
    for (int g = 0; g < 2; g++) {
        const float* feat = g ? feat2 : feat1;
        const float* Ap   = g ? A2p : A1p;
        float* ev         = g ? e2 : e1;
        const float* cv   = col + g * ROWS;
        split_rm<<<32768, 256>>>(feat, bfA, 8192LL * 1024, PFEAT);
        split_tr<<<dim3(64, 32, 1), T32>>>(W0a, bfB, 1024, 2048, PW0);
        tgemm<<<dim3(64, 16, 1), 256, SMEMT>>>(8192, 2048, 1024, bfA, 1024, PFEAT, 0,
            bfB, 1024, PW0, 0, ax, 2048, 0, b0a, 1, cv, 0, 0, 0);
        split_tr<<<dim3(64, 32, 1), T32>>>(W0u, bfB, 1024, 2048, PW0);
        tgemm<<<dim3(64, 16, 1), 256, SMEMT>>>(8192, 2048, 1024, bfA, 1024, PFEAT, 0,
            bfB, 1024, PW0, 0, ux, 2048, 0, b0u, 1, 0, 0, 0, 0);
        split_rm<<<8192, 256>>>(Ap, bfA, 2097152LL, PADJ);
        split_tr<<<dim3(64, 8, 32), T32>>>(ax, bfB2, 256, 2048, PBIG);
        tgemm<<<dim3(2, 16, 32), 256, SMEMT>>>(256, 2048, 256, bfA, 256, PADJ, SS,
            bfB2, 256, PBIG, SE, ev, 2048, SE, 0, 0, 0, ux, 2048, SE);
    }

    /* affinity 0 + sinkhorn */
    split_rm<<<65536, 256>>>(e1, bfA, (long long)ROWS * CH, PBIG);
    split_tr<<<dim3(64, 64, 1), T32>>>(Aaff0, bfB, 2048, 2048, PAAF);
    tgemm<<<dim3(64, 16, 1), 256, SMEMT>>>(8192, 2048, 2048, bfA, 2048, PBIG, 0,
        bfB, 2048, PAAF, 0, tb, 2048, 0, 0, 0, 0, 0, 0, 0);
    split_rm<<<65536, 256>>>(tb, bfA, (long long)ROWS * CH, PBIG);
    split_rm<<<65536, 256>>>(e2, bfB, (long long)ROWS * CH, PBIG);
    tgemm<<<dim3(2, 2, 32), 256, SMEMT>>>(256, 256, 2048, bfA, 2048, PBIG, SE,
        bfB, 2048, PBIG, SE, sb, 256, SS, 0, 0, 0, 0, 0, 0);
    sinkhorn_kernel<<<32, 1024>>>(sb, sb, n1p, skp);

    /* cross update: m1 = e1@WcT + (s@e2)@WcB + bc ; m2 = e2@WcT + (sT@e1)@WcB + bc */
    split_rm<<<8192, 256>>>(sb, bfA, 2097152LL, PSB);
    split_tr<<<dim3(64, 8, 32), T32>>>(e2, bfB2, 256, 2048, PBIG);
    tgemm<<<dim3(2, 16, 32), 256, SMEMT>>>(256, 2048, 256, bfA, 256, PSB, SS,
        bfB2, 256, PBIG, SE, tb, 2048, SE, 0, 0, 0, 0, 0, 0);     /* u -> tb */
    split_tr<<<dim3(64, 128, 1), T32>>>(Wc, bfB, 4096, 2048, PWC);
    split_rm<<<65536, 256>>>(e1, bfA, (long long)ROWS * CH, PBIG);
    tgemm<<<dim3(64, 16, 1), 256, SMEMT>>>(8192, 2048, 2048, bfA, 2048, PBIG, 0,
        bfB, 4096, PWC, 0, m1, 2048, 0, bc, 0, 0, 0, 0, 0);
    split_rm<<<65536, 256>>>(tb, bfA, (long long)ROWS * CH, PBIG);
    tgemm<<<dim3(64, 16, 1), 256, SMEMT>>>(8192, 2048, 2048, bfA, 2048, PBIG, 0,
        bfB + 2048, 4096, PWC, 0, m1, 2048, 0, 0, 0, 0, m1, 2048, 0);
    split_tr<<<dim3(8, 8, 32), T32>>>(sb, bfA, 256, 256, PSB);    /* sT planes */
    split_tr<<<dim3(64, 8, 32), T32>>>(e1, bfB2, 256, 2048, PBIG);
    tgemm<<<dim3(2, 16, 32), 256, SMEMT>>>(256, 2048, 256, bfA, 256, PSB, SS,
        bfB2, 256, PBIG, SE, ax, 2048, SE, 0, 0, 0, 0, 0, 0);     /* v -> ax */
    split_rm<<<65536, 256>>>(e2, bfA, (long long)ROWS * CH, PBIG);
    tgemm<<<dim3(64, 16, 1), 256, SMEMT>>>(8192, 2048, 2048, bfA, 2048, PBIG, 0,
        bfB, 4096, PWC, 0, m2, 2048, 0, bc, 0, 0, 0, 0, 0);
    split_rm<<<65536, 256>>>(ax, bfA, (long long)ROWS * CH, PBIG);
    tgemm<<<dim3(64, 16, 1), 256, SMEMT>>>(8192, 2048, 2048, bfA, 2048, PBIG, 0,
        bfB + 2048, 4096, PWC, 0, m2, 2048, 0, 0, 0, 0, m2, 2048, 0);

    /* gconv layer 1 */
    for (int g = 0; g < 2; g++) {
        const float* mv = g ? m2 : m1;
        const float* Ap = g ? A2p : A1p;
        float* ev       = g ? e2 : e1;
        const float* cv = col + g * ROWS;
        split_rm<<<65536, 256>>>(mv, bfA, (long long)ROWS * CH, PBIG);
        split_tr<<<dim3(64, 64, 1), T32>>>(W1a, bfB, 2048, 2048, PAAF);
        tgemm<<<dim3(64, 16, 1), 256, SMEMT>>>(8192, 2048, 2048, bfA, 2048, PBIG, 0,
            bfB, 2048, PAAF, 0, ax, 2048, 0, b1a, 1, cv, 0, 0, 0);
        split_tr<<<dim3(64, 64, 1), T32>>>(W1u, bfB, 2048, 2048, PAAF);
        tgemm<<<dim3(64, 16, 1), 256, SMEMT>>>(8192, 2048, 2048, bfA, 2048, PBIG, 0,
            bfB, 2048, PAAF, 0, ux, 2048, 0, b1u, 1, 0, 0, 0, 0);
        split_rm<<<8192, 256>>>(Ap, bfA, 2097152LL, PADJ);
        split_tr<<<dim3(64, 8, 32), T32>>>(ax, bfB2, 256, 2048, PBIG);
        tgemm<<<dim3(2, 16, 32), 256, SMEMT>>>(256, 2048, 256, bfA, 256, PADJ, SS,
            bfB2, 256, PBIG, SE, ev, 2048, SE, 0, 0, 0, ux, 2048, SE);
    }

    /* affinity 1 + final sinkhorn */
    split_rm<<<65536, 256>>>(e1, bfA, (long long)ROWS * CH, PBIG);
    split_tr<<<dim3(64, 64, 1), T32>>>(Aaff1, bfB, 2048, 2048, PAAF);
    tgemm<<<dim3(64, 16, 1), 256, SMEMT>>>(8192, 2048, 2048, bfA, 2048, PBIG, 0,
        bfB, 2048, PAAF, 0, tb, 2048, 0, 0, 0, 0, 0, 0, 0);
    split_rm<<<65536, 256>>>(tb, bfA, (long long)ROWS * CH, PBIG);
    split_rm<<<65536, 256>>>(e2, bfB, (long long)ROWS * CH, PBIG);
    tgemm<<<dim3(2, 2, 32), 256, SMEMT>>>(256, 256, 2048, bfA, 2048, PBIG, SE,
        bfB, 2048, PBIG, SE, sb, 256, SS, 0, 0, 0, 0, 0, 0);
    sinkhorn_kernel<<<32, 1024>>>(sb, outp, n1p, skp);
}

// round 10
// speedup vs baseline: 1.5062x; 1.4279x over previous
#include <cuda_runtime.h>
#include <cuda_bf16.h>

#define NEGV (-1e9f)
#define B_   32
#define N_   256
#define CH   2048
#define ROWS (B_ * N_)                 /* 8192 */
#define KT   16

/* plane strides (elements) */
#define PFEAT 8388608LL                /* 8192x1024 */
#define PW0   2097152LL                /* 1024x2048 tr-> 2048x1024 */
#define PADJ  2097152LL                /* 32x256x256 */
#define PBIG  16777216LL               /* 8192x2048 class */
#define PAAF  4194304LL                /* 2048x2048 */
#define PWC   8388608LL                /* 2048x4096 (Wc tr) */
#define PSB   2097152LL                /* 32x256x256 */

/* smem geometry: padded rows 24 bf16 = 48 B; 4 plane-tiles per stage */
#define APAD_B  48
#define ATILE_B (128 * APAD_B)         /* 6144 B */
#define STG_B   (4 * ATILE_B)          /* 24576 B */
#define NSTG    3
#define SMEMT   (NSTG * STG_B)         /* 73728 B */

/* ------------- scratch (device globals) --------------------------------- */
__device__ __nv_bfloat16 g_bfA [2LL * 8192 * 2048];
__device__ __nv_bfloat16 g_bfB [2LL * 8192 * 2048];
__device__ __nv_bfloat16 g_bfB2[2LL * 8192 * 2048];
__device__ float g_ax[ROWS * CH];
__device__ float g_ux[ROWS * CH];
__device__ float g_e1[ROWS * CH];
__device__ float g_e2[ROWS * CH];
__device__ float g_tb[ROWS * CH];
__device__ float g_m1[ROWS * CH];
__device__ float g_m2[ROWS * CH];
__device__ float g_sb[B_ * N_ * N_];
__device__ float g_col[2 * ROWS];

/* ------------- low-level helpers ---------------------------------------- */
__device__ __forceinline__ void cpasync16(unsigned saddr, const void* g) {
    asm volatile("cp.async.ca.shared.global [%0], [%1], 16;" :: "r"(saddr), "l"(g));
}
#define LDSM4(r, addr) \
    asm volatile("ldmatrix.sync.aligned.m8n8.x4.shared.b16 {%0,%1,%2,%3}, [%4];" \
        : "=r"((r)[0]), "=r"((r)[1]), "=r"((r)[2]), "=r"((r)[3]) : "r"(addr))
#define MMA(d, a, b0v, b1v) \
    asm volatile("mma.sync.aligned.m16n8k16.row.col.f32.bf16.bf16.f32 " \
        "{%0,%1,%2,%3},{%4,%5,%6,%7},{%8,%9},{%0,%1,%2,%3};" \
        : "+f"((d)[0]), "+f"((d)[1]), "+f"((d)[2]), "+f"((d)[3]) \
        : "r"((a)[0]), "r"((a)[1]), "r"((a)[2]), "r"((a)[3]), "r"(b0v), "r"(b1v))

/* ------------- tensor GEMM: C = A @ Bop^T, bf16x2 split, 4 products.
 * A planes: [M][lda] bf16 x2 (plane stride aPS); Bop planes: [N][ldb] x2.
 * CTA tile 128x128, 8 warps (warp tile 32x64), K-step 16, 3-stage cp.async.
 * a0*b0 -> cm (dominant, clean fp32 chain); a0b1+a1b0+a1b1 -> cc.
 * Residual (uncaptured 2^-18 planes) ~7.6e-6 rel == below fp32 chain noise. */
__global__ __launch_bounds__(256) void tgemm(
    int M, int N, int K,
    const __nv_bfloat16* __restrict__ A, int lda, long long aPS, long long sAb,
    const __nv_bfloat16* __restrict__ B, int ldb, long long bPS, long long sBb,
    float* __restrict__ C, int ldc, long long sCb,
    const float* __restrict__ bias, int relu,
    const float* __restrict__ rowscale,
    const float* __restrict__ addend, int ldadd, long long sAddb)
{
    extern __shared__ unsigned char smem[];
    const int bz = blockIdx.z;
    A += (long long)bz * sAb;
    B += (long long)bz * sBb;
    C += (long long)bz * sCb;
    if (addend) addend += (long long)bz * sAddb;
    const int m0 = blockIdx.x * 128, n0 = blockIdx.y * 128;
    const int tid = threadIdx.x, lane = tid & 31, wid = tid >> 5;
    const unsigned sb = (unsigned)__cvta_generic_to_shared(smem);

    /* cp.async mapping: thread -> (row, 16B chunk) for both A and B tiles */
    const int cr = tid >> 1, ck = tid & 1;
    const __nv_bfloat16* aG = A + (long long)(m0 + cr) * lda + ck * 8;
    const __nv_bfloat16* bG = B + (long long)(n0 + cr) * ldb + ck * 8;
    const unsigned aS = sb + cr * APAD_B + ck * 16;
    const unsigned bS = sb + 2 * ATILE_B + cr * APAD_B + ck * 16;

    const int nst = K >> 4;
#define TISSUE(t, st) do {                                                \
        long long ko = (long long)(t) * KT;                               \
        _Pragma("unroll")                                                 \
        for (int p = 0; p < 2; p++) {                                     \
            cpasync16(aS + (st) * STG_B + p * ATILE_B, aG + p * aPS + ko);\
            cpasync16(bS + (st) * STG_B + p * ATILE_B, bG + p * bPS + ko);\
        }                                                                 \
        asm volatile("cp.async.commit_group;");                           \
    } while (0)

    TISSUE(0, 0);
    if (nst > 1) TISSUE(1, 1);

    float cm[2][8][4], cc[2][8][4];
#pragma unroll
    for (int i = 0; i < 2; i++)
#pragma unroll
        for (int j = 0; j < 8; j++)
#pragma unroll
            for (int k = 0; k < 4; k++) { cm[i][j][k] = 0.f; cc[i][j][k] = 0.f; }

    const int mw = (wid & 3) * 32, nw = (wid >> 2) * 64;
    const int q = lane >> 3, rl = lane & 7;
    const unsigned aoff = (mw + rl + (q & 1) * 8) * APAD_B + (q >> 1) * 16;
    const unsigned boff = 2 * ATILE_B + (nw + rl + (q & 1) * 8) * APAD_B + (q >> 1) * 16;

    int st = 0;
    for (int t = 0; t < nst; ++t) {
        if (t + 1 < nst) asm volatile("cp.async.wait_group 1;");
        else             asm volatile("cp.async.wait_group 0;");
        __syncthreads();
        if (t + 2 < nst) {
            int s2 = st + 2; if (s2 >= NSTG) s2 -= NSTG;
            TISSUE(t + 2, s2);
        }
        const unsigned sa = sb + st * STG_B + aoff;
        const unsigned sB2 = sb + st * STG_B + boff;

        unsigned a[2][2][4];
#pragma unroll
        for (int p = 0; p < 2; p++)
#pragma unroll
            for (int mi = 0; mi < 2; mi++)
                LDSM4(a[p][mi], sa + p * ATILE_B + mi * 16 * APAD_B);

#pragma unroll
        for (int ng = 0; ng < 4; ng++) {
            unsigned bf[2][4];
#pragma unroll
            for (int p = 0; p < 2; p++)
                LDSM4(bf[p], sB2 + p * ATILE_B + ng * 16 * APAD_B);
#pragma unroll
            for (int mi = 0; mi < 2; mi++)
#pragma unroll
                for (int j = 0; j < 2; j++) {
                    float* dm = cm[mi][ng * 2 + j];
                    float* dc = cc[mi][ng * 2 + j];
                    MMA(dm, a[0][mi], bf[0][j], bf[0][j + 2]);
                    MMA(dc, a[0][mi], bf[1][j], bf[1][j + 2]);
                    MMA(dc, a[1][mi], bf[0][j], bf[0][j + 2]);
                    MMA(dc, a[1][mi], bf[1][j], bf[1][j + 2]);
                }
        }
        __syncthreads();
        if (++st == NSTG) st = 0;
    }
#undef TISSUE

    /* epilogue: c-frag (mi): rows g/g+8, cols tg*2, tg*2+1 */
    const int g = lane >> 2, tg = lane & 3;
#pragma unroll
    for (int mi = 0; mi < 2; mi++) {
        const int r0 = m0 + mw + mi * 16 + g;
        const int r1 = r0 + 8;
        const float rs0 = rowscale ? rowscale[r0] : 1.f;
        const float rs1 = rowscale ? rowscale[r1] : 1.f;
#pragma unroll
        for (int nf = 0; nf < 8; nf++) {
            const int col = n0 + nw + nf * 8 + tg * 2;
            float o0 = cm[mi][nf][0] + cc[mi][nf][0];
            float o1 = cm[mi][nf][1] + cc[mi][nf][1];
            float o2 = cm[mi][nf][2] + cc[mi][nf][2];
            float o3 = cm[mi][nf][3] + cc[mi][nf][3];
            if (bias) {
                float bv0 = bias[col], bv1 = bias[col + 1];
                o0 += bv0; o1 += bv1; o2 += bv0; o3 += bv1;
            }
            if (relu) {
                o0 = fmaxf(o0, 0.f); o1 = fmaxf(o1, 0.f);
                o2 = fmaxf(o2, 0.f); o3 = fmaxf(o3, 0.f);
            }
            o0 *= rs0; o1 *= rs0; o2 *= rs1; o3 *= rs1;
            if (addend) {
                o0 += addend[(long long)r0 * ldadd + col];
                o1 += addend[(long long)r0 * ldadd + col + 1];
                o2 += addend[(long long)r1 * ldadd + col];
                o3 += addend[(long long)r1 * ldadd + col + 1];
            }
            *(float2*)(C + (long long)r0 * ldc + col) = make_float2(o0, o1);
            *(float2*)(C + (long long)r1 * ldc + col) = make_float2(o2, o3);
        }
    }
}

/* ------------- fp32 -> 2 bf16 planes ------------------------------------ */
__device__ __forceinline__ void split2(float v, __nv_bfloat16& b0, __nv_bfloat16& b1) {
    b0 = __float2bfloat16(v);
    b1 = __float2bfloat16(v - __bfloat162float(b0));
}
__global__ void split_rm(const float* __restrict__ in, __nv_bfloat16* __restrict__ out,
                         long long n, long long PS)
{
    long long i = (long long)blockIdx.x * blockDim.x + threadIdx.x;
    if (i >= n) return;
    __nv_bfloat16 b0, b1;
    split2(in[i], b0, b1);
    out[i] = b0; out[PS + i] = b1;
}
/* transpose + split: in [z][R][C] fp32 -> planes [z][C][R] bf16 */
__global__ void split_tr(const float* __restrict__ in, __nv_bfloat16* __restrict__ out,
                         int R, int C, long long PS)
{
    __shared__ float t[32][33];
    const long long zo = (long long)blockIdx.z * R * C;
    const float* ip = in + zo;
    __nv_bfloat16* op = out + zo;
    int x = blockIdx.x * 32 + threadIdx.x;
    int y0 = blockIdx.y * 32 + threadIdx.y;
#pragma unroll
    for (int j = 0; j < 32; j += 8)
        t[threadIdx.y + j][threadIdx.x] = ip[(long long)(y0 + j) * C + x];
    __syncthreads();
    int xo = blockIdx.y * 32 + threadIdx.x;
    int yo = blockIdx.x * 32 + threadIdx.y;
#pragma unroll
    for (int j = 0; j < 32; j += 8) {
        __nv_bfloat16 b0, b1;
        split2(t[threadIdx.x][threadIdx.y + j], b0, b1);
        long long oi = (long long)(yo + j) * R + xo;
        op[oi] = b0; op[PS + oi] = b1;
    }
}

/* ------------- colnorm --------------------------------------------------- */
__global__ void colnorm_kernel(const float* __restrict__ A, float* __restrict__ inv)
{
    int g = blockIdx.x * blockDim.x + threadIdx.x;
    int b = g >> 8, m = g & 255;
    const float* base = A + (long long)b * 65536 + m;
    float s = 0.f;
#pragma unroll 8
    for (int n = 0; n < 256; n++) s += fabsf(base[n * 256]);
    inv[g] = 1.f / fmaxf(s, 1e-12f);
}

/* ------------- masked Sinkhorn ------------------------------------------- */
__global__ __launch_bounds__(1024) void sinkhorn_kernel(
    float* __restrict__ buf, float* __restrict__ out,
    const int* __restrict__ n1, const int* __restrict__ iters_ptr)
{
    __shared__ float red[4 * 256];
    __shared__ float lsebuf[256];
    const int b = blockIdx.x;
    float* Mb = buf + (long long)b * 65536;
    const int nv = n1[b];
    const int iters = *iters_ptr;
    const int tid = threadIdx.x;
    const int warp = tid >> 5, lane = tid & 31;

    for (int idx = tid; idx < 65536; idx += 1024) {
        int r = idx >> 8;
        float v = Mb[idx];
        Mb[idx] = (r < nv) ? v / 0.05f : NEGV;
    }
    __syncthreads();
    for (int it = 0; it < iters; ++it) {
        if ((it & 1) == 0) {
            for (int r = warp; r < 256; r += 32) {
                float* rp = Mb + (r << 8);
                float v[8];
#pragma unroll
                for (int j = 0; j < 8; j++) v[j] = rp[lane + (j << 5)];
                float mx = v[0];
#pragma unroll
                for (int j = 1; j < 8; j++) mx = fmaxf(mx, v[j]);
#pragma unroll
                for (int o = 16; o > 0; o >>= 1)
                    mx = fmaxf(mx, __shfl_xor_sync(0xffffffffu, mx, o));
                float sm = 0.f;
#pragma unroll
                for (int j = 0; j < 8; j++) sm += expf(v[j] - mx);
#pragma unroll
                for (int o = 16; o > 0; o >>= 1)
                    sm += __shfl_xor_sync(0xffffffffu, sm, o);
                float lse = mx + logf(sm);
                bool ok = r < nv;
#pragma unroll
                for (int j = 0; j < 8; j++)
                    rp[lane + (j << 5)] = ok ? (v[j] - lse) : NEGV;
            }
            __syncthreads();
        } else {
            const int c = tid & 255, g = tid >> 8;
            float pm = NEGV;
            for (int r = g; r < 256; r += 4) pm = fmaxf(pm, Mb[(r << 8) + c]);
            red[(g << 8) + c] = pm;
            __syncthreads();
            if (tid < 256)
                lsebuf[tid] = fmaxf(fmaxf(red[tid], red[256 + tid]),
                                    fmaxf(red[512 + tid], red[768 + tid]));
            __syncthreads();
            float cm = lsebuf[c];
            float ps = 0.f;
            for (int r = g; r < 256; r += 4) ps += expf(Mb[(r << 8) + c] - cm);
            red[(g << 8) + c] = ps;
            __syncthreads();
            if (tid < 256)
                lsebuf[tid] = lsebuf[tid] + logf(red[tid] + red[256 + tid] +
                                                 red[512 + tid] + red[768 + tid]);
            __syncthreads();
            for (int idx = tid; idx < 65536; idx += 1024) {
                int r = idx >> 8, cc2 = idx & 255;
                Mb[idx] = (r < nv) ? (Mb[idx] - lsebuf[cc2]) : NEGV;
            }
            __syncthreads();
        }
    }
    float* ob = out + (long long)b * 65536;
    for (int idx = tid; idx < 65536; idx += 1024)
        ob[idx] = expf(Mb[idx]);
}

/* ------------- orchestration -------------------------------------------- */
extern "C" void kernel_launch(void* const* d_in, const int* in_sizes, int n_in,
                              void* d_out, int out_size)
{
    (void)in_sizes; (void)n_in; (void)out_size;
    const float* feat1 = (const float*)d_in[0];
    const float* feat2 = (const float*)d_in[1];
    const float* A1p   = (const float*)d_in[2];
    const float* A2p   = (const float*)d_in[3];
    const int*   n1p   = (const int*)d_in[4];
    const int*   skp   = (const int*)d_in[7];
    const float* W0a = (const float*)d_in[8],  *b0a = (const float*)d_in[9];
    const float* W0u = (const float*)d_in[10], *b0u = (const float*)d_in[11];
    const float* W1a = (const float*)d_in[12], *b1a = (const float*)d_in[13];
    const float* W1u = (const float*)d_in[14], *b1u = (const float*)d_in[15];
    const float* Wc  = (const float*)d_in[16], *bc  = (const float*)d_in[17];
    const float* Aaff0 = (const float*)d_in[18];
    const float* Aaff1 = (const float*)d_in[19];
    float* outp = (float*)d_out;

    __nv_bfloat16 *bfA, *bfB, *bfB2;
    float *ax, *ux, *e1, *e2, *tb, *m1, *m2, *sb, *col;
    cudaGetSymbolAddress((void**)&bfA,  g_bfA);
    cudaGetSymbolAddress((void**)&bfB,  g_bfB);
    cudaGetSymbolAddress((void**)&bfB2, g_bfB2);
    cudaGetSymbolAddress((void**)&ax,  g_ax);
    cudaGetSymbolAddress((void**)&ux,  g_ux);
    cudaGetSymbolAddress((void**)&e1,  g_e1);
    cudaGetSymbolAddress((void**)&e2,  g_e2);
    cudaGetSymbolAddress((void**)&tb,  g_tb);
    cudaGetSymbolAddress((void**)&m1,  g_m1);
    cudaGetSymbolAddress((void**)&m2,  g_m2);
    cudaGetSymbolAddress((void**)&sb,  g_sb);
    cudaGetSymbolAddress((void**)&col, g_col);

    cudaFuncSetAttribute(tgemm, cudaFuncAttributeMaxDynamicSharedMemorySize, SMEMT);

    const dim3 T32(32, 8);
    const long long SE = 524288;            /* 256*2048 per-batch */
    const long long SS = 65536;

    colnorm_kernel<<<32, 256>>>(A1p, col);
    colnorm_kernel<<<32, 256>>>(A2p, col + ROWS);

    /* gconv layer 0 : graph g = 1,2 */
    for (int g = 0; g < 2; g++) {
        const float* feat = g ? feat2 : feat1;
        const float* Ap   = g ? A2p : A1p;
        float* ev         = g ? e2 : e1;
        const float* cv   = col + g * ROWS;
        split_rm<<<32768, 256>>>(feat, bfA, 8192LL * 1024, PFEAT);
        split_tr<<<dim3(64, 32, 1), T32>>>(W0a, bfB, 1024, 2048, PW0);
        tgemm<<<dim3(64, 16, 1), 256, SMEMT>>>(8192, 2048, 1024, bfA, 1024, PFEAT, 0,
            bfB, 1024, PW0, 0, ax, 2048, 0, b0a, 1, cv, 0, 0, 0);
        split_tr<<<dim3(64, 32, 1), T32>>>(W0u, bfB, 1024, 2048, PW0);
        tgemm<<<dim3(64, 16, 1), 256, SMEMT>>>(8192, 2048, 1024, bfA, 1024, PFEAT, 0,
            bfB, 1024, PW0, 0, ux, 2048, 0, b0u, 1, 0, 0, 0, 0);
        split_rm<<<8192, 256>>>(Ap, bfA, 2097152LL, PADJ);
        split_tr<<<dim3(64, 8, 32), T32>>>(ax, bfB2, 256, 2048, PBIG);
        tgemm<<<dim3(2, 16, 32), 256, SMEMT>>>(256, 2048, 256, bfA, 256, PADJ, SS,
            bfB2, 256, PBIG, SE, ev, 2048, SE, 0, 0, 0, ux, 2048, SE);
    }

    /* affinity 0 + sinkhorn */
    split_rm<<<65536, 256>>>(e1, bfA, (long long)ROWS * CH, PBIG);
    split_tr<<<dim3(64, 64, 1), T32>>>(Aaff0, bfB, 2048, 2048, PAAF);
    tgemm<<<dim3(64, 16, 1), 256, SMEMT>>>(8192, 2048, 2048, bfA, 2048, PBIG, 0,
        bfB, 2048, PAAF, 0, tb, 2048, 0, 0, 0, 0, 0, 0, 0);
    split_rm<<<65536, 256>>>(tb, bfA, (long long)ROWS * CH, PBIG);
    split_rm<<<65536, 256>>>(e2, bfB, (long long)ROWS * CH, PBIG);
    tgemm<<<dim3(2, 2, 32), 256, SMEMT>>>(256, 256, 2048, bfA, 2048, PBIG, SE,
        bfB, 2048, PBIG, SE, sb, 256, SS, 0, 0, 0, 0, 0, 0);
    sinkhorn_kernel<<<32, 1024>>>(sb, sb, n1p, skp);

    /* cross update: m1 = e1@WcT + (s@e2)@WcB + bc ; m2 = e2@WcT + (sT@e1)@WcB + bc */
    split_rm<<<8192, 256>>>(sb, bfA, 2097152LL, PSB);
    split_tr<<<dim3(64, 8, 32), T32>>>(e2, bfB2, 256, 2048, PBIG);
    tgemm<<<dim3(2, 16, 32), 256, SMEMT>>>(256, 2048, 256, bfA, 256, PSB, SS,
        bfB2, 256, PBIG, SE, tb, 2048, SE, 0, 0, 0, 0, 0, 0);     /* u -> tb */
    split_tr<<<dim3(64, 128, 1), T32>>>(Wc, bfB, 4096, 2048, PWC);
    split_rm<<<65536, 256>>>(e1, bfA, (long long)ROWS * CH, PBIG);
    tgemm<<<dim3(64, 16, 1), 256, SMEMT>>>(8192, 2048, 2048, bfA, 2048, PBIG, 0,
        bfB, 4096, PWC, 0, m1, 2048, 0, bc, 0, 0, 0, 0, 0);
    split_rm<<<65536, 256>>>(tb, bfA, (long long)ROWS * CH, PBIG);
    tgemm<<<dim3(64, 16, 1), 256, SMEMT>>>(8192, 2048, 2048, bfA, 2048, PBIG, 0,
        bfB + 2048, 4096, PWC, 0, m1, 2048, 0, 0, 0, 0, m1, 2048, 0);
    split_tr<<<dim3(8, 8, 32), T32>>>(sb, bfA, 256, 256, PSB);    /* sT planes */
    split_tr<<<dim3(64, 8, 32), T32>>>(e1, bfB2, 256, 2048, PBIG);
    tgemm<<<dim3(2, 16, 32), 256, SMEMT>>>(256, 2048, 256, bfA, 256, PSB, SS,
        bfB2, 256, PBIG, SE, ax, 2048, SE, 0, 0, 0, 0, 0, 0);     /* v -> ax */
    split_rm<<<65536, 256>>>(e2, bfA, (long long)ROWS * CH, PBIG);
    tgemm<<<dim3(64, 16, 1), 256, SMEMT>>>(8192, 2048, 2048, bfA, 2048, PBIG, 0,
        bfB, 4096, PWC, 0, m2, 2048, 0, bc, 0, 0, 0, 0, 0);
    split_rm<<<65536, 256>>>(ax, bfA, (long long)ROWS * CH, PBIG);
    tgemm<<<dim3(64, 16, 1), 256, SMEMT>>>(8192, 2048, 2048, bfA, 2048, PBIG, 0,
        bfB + 2048, 4096, PWC, 0, m2, 2048, 0, 0, 0, 0, m2, 2048, 0);

    /* gconv layer 1 */
    for (int g = 0; g < 2; g++) {
        const float* mv = g ? m2 : m1;
        const float* Ap = g ? A2p : A1p;
        float* ev       = g ? e2 : e1;
        const float* cv = col + g * ROWS;
        split_rm<<<65536, 256>>>(mv, bfA, (long long)ROWS * CH, PBIG);
        split_tr<<<dim3(64, 64, 1), T32>>>(W1a, bfB, 2048, 2048, PAAF);
        tgemm<<<dim3(64, 16, 1), 256, SMEMT>>>(8192, 2048, 2048, bfA, 2048, PBIG, 0,
            bfB, 2048, PAAF, 0, ax, 2048, 0, b1a, 1, cv, 0, 0, 0);
        split_tr<<<dim3(64, 64, 1), T32>>>(W1u, bfB, 2048, 2048, PAAF);
        tgemm<<<dim3(64, 16, 1), 256, SMEMT>>>(8192, 2048, 2048, bfA, 2048, PBIG, 0,
            bfB, 2048, PAAF, 0, ux, 2048, 0, b1u, 1, 0, 0, 0, 0);
        split_rm<<<8192, 256>>>(Ap, bfA, 2097152LL, PADJ);
        split_tr<<<dim3(64, 8, 32), T32>>>(ax, bfB2, 256, 2048, PBIG);
        tgemm<<<dim3(2, 16, 32), 256, SMEMT>>>(256, 2048, 256, bfA, 256, PADJ, SS,
            bfB2, 256, PBIG, SE, ev, 2048, SE, 0, 0, 0, ux, 2048, SE);
    }

    /* affinity 1 + final sinkhorn */
    split_rm<<<65536, 256>>>(e1, bfA, (long long)ROWS * CH, PBIG);
    split_tr<<<dim3(64, 64, 1), T32>>>(Aaff1, bfB, 2048, 2048, PAAF);
    tgemm<<<dim3(64, 16, 1), 256, SMEMT>>>(8192, 2048, 2048, bfA, 2048, PBIG, 0,
        bfB, 2048, PAAF, 0, tb, 2048, 0, 0, 0, 0, 0, 0, 0);
    split_rm<<<65536, 256>>>(tb, bfA, (long long)ROWS * CH, PBIG);
    split_rm<<<65536, 256>>>(e2, bfB, (long long)ROWS * CH, PBIG);
    tgemm<<<dim3(2, 2, 32), 256, SMEMT>>>(256, 256, 2048, bfA, 2048, PBIG, SE,
        bfB, 2048, PBIG, SE, sb, 256, SS, 0, 0, 0, 0, 0, 0);
    sinkhorn_kernel<<<32, 1024>>>(sb, outp, n1p, skp);
}

// round 11
// speedup vs baseline: 1.8268x; 1.2128x over previous
#include <cuda_runtime.h>
#include <cuda_bf16.h>

#define NEGV (-1e9f)
#define B_   32
#define N_   256
#define CH   2048
#define ROWS (B_ * N_)                 /* 8192 */
#define KT   16

/* plane strides (elements) */
#define PFEAT 8388608LL                /* 8192x1024 */
#define PW0   2097152LL                /* 1024x2048 tr-> 2048x1024 */
#define PADJ  2097152LL                /* 32x256x256 */
#define PBIG  16777216LL               /* 8192x2048 class */
#define PAAF  4194304LL                /* 2048x2048 */
#define PWC   8388608LL                /* 2048x4096 (Wc tr) */
#define PSB   2097152LL                /* 32x256x256 */

/* smem geometry: padded rows 24 bf16 = 48 B; 4 plane-tiles per stage */
#define APAD_B  48
#define ATILE_B (128 * APAD_B)         /* 6144 B */
#define STG_B   (4 * ATILE_B)          /* 24576 B */
#define NSTG    3
#define SMEMT   (NSTG * STG_B)         /* 73728 B */

/* ------------- scratch (device globals) --------------------------------- */
__device__ __nv_bfloat16 g_bfA [2LL * 8192 * 2048];
__device__ __nv_bfloat16 g_bfB [2LL * 8192 * 2048];
__device__ __nv_bfloat16 g_bfB2[2LL * 8192 * 2048];
__device__ float g_ax[ROWS * CH];
__device__ float g_ux[ROWS * CH];
__device__ float g_e1[ROWS * CH];
__device__ float g_e2[ROWS * CH];
__device__ float g_tb[ROWS * CH];
__device__ float g_m1[ROWS * CH];
__device__ float g_m2[ROWS * CH];
__device__ float g_sb[B_ * N_ * N_];
__device__ float g_col[2 * ROWS];

/* ------------- low-level helpers ---------------------------------------- */
__device__ __forceinline__ void cpasync16(unsigned saddr, const void* g) {
    asm volatile("cp.async.ca.shared.global [%0], [%1], 16;" :: "r"(saddr), "l"(g));
}
#define LDSM4(r, addr) \
    asm volatile("ldmatrix.sync.aligned.m8n8.x4.shared.b16 {%0,%1,%2,%3}, [%4];" \
        : "=r"((r)[0]), "=r"((r)[1]), "=r"((r)[2]), "=r"((r)[3]) : "r"(addr))
#define MMA(d, a, b0v, b1v) \
    asm volatile("mma.sync.aligned.m16n8k16.row.col.f32.bf16.bf16.f32 " \
        "{%0,%1,%2,%3},{%4,%5,%6,%7},{%8,%9},{%0,%1,%2,%3};" \
        : "+f"((d)[0]), "+f"((d)[1]), "+f"((d)[2]), "+f"((d)[3]) \
        : "r"((a)[0]), "r"((a)[1]), "r"((a)[2]), "r"((a)[3]), "r"(b0v), "r"(b1v))

/* ------------- tensor GEMM: C = A @ Bop^T, bf16x2 split, 3 products.
 * A planes: [M][lda] bf16 x2 (plane stride aPS); Bop planes: [N][ldb] x2.
 * CTA tile 128x128, 8 warps (warp tile 32x64), K-step 16, 3-stage cp.async.
 * a0*b0 -> cm (dominant, clean fp32 chain); a0b1 + a1b0 -> cc.
 * Dropped terms (a1b1 + 2^-18 planes) ~6e-6 rel -> below threshold impact. */
__global__ __launch_bounds__(256) void tgemm(
    int M, int N, int K,
    const __nv_bfloat16* __restrict__ A, int lda, long long aPS, long long sAb,
    const __nv_bfloat16* __restrict__ B, int ldb, long long bPS, long long sBb,
    float* __restrict__ C, int ldc, long long sCb,
    const float* __restrict__ bias, int relu,
    const float* __restrict__ rowscale,
    const float* __restrict__ addend, int ldadd, long long sAddb)
{
    extern __shared__ unsigned char smem[];
    const int bz = blockIdx.z;
    A += (long long)bz * sAb;
    B += (long long)bz * sBb;
    C += (long long)bz * sCb;
    if (addend) addend += (long long)bz * sAddb;
    const int m0 = blockIdx.x * 128, n0 = blockIdx.y * 128;
    const int tid = threadIdx.x, lane = tid & 31, wid = tid >> 5;
    const unsigned sb = (unsigned)__cvta_generic_to_shared(smem);

    /* cp.async mapping: thread -> (row, 16B chunk) for both A and B tiles */
    const int cr = tid >> 1, ck = tid & 1;
    const __nv_bfloat16* aG = A + (long long)(m0 + cr) * lda + ck * 8;
    const __nv_bfloat16* bG = B + (long long)(n0 + cr) * ldb + ck * 8;
    const unsigned aS = sb + cr * APAD_B + ck * 16;
    const unsigned bS = sb + 2 * ATILE_B + cr * APAD_B + ck * 16;

    const int nst = K >> 4;
#define TISSUE(t, st) do {                                                \
        long long ko = (long long)(t) * KT;                               \
        _Pragma("unroll")                                                 \
        for (int p = 0; p < 2; p++) {                                     \
            cpasync16(aS + (st) * STG_B + p * ATILE_B, aG + p * aPS + ko);\
            cpasync16(bS + (st) * STG_B + p * ATILE_B, bG + p * bPS + ko);\
        }                                                                 \
        asm volatile("cp.async.commit_group;");                           \
    } while (0)

    TISSUE(0, 0);
    if (nst > 1) TISSUE(1, 1);

    float cm[2][8][4], cc[2][8][4];
#pragma unroll
    for (int i = 0; i < 2; i++)
#pragma unroll
        for (int j = 0; j < 8; j++)
#pragma unroll
            for (int k = 0; k < 4; k++) { cm[i][j][k] = 0.f; cc[i][j][k] = 0.f; }

    const int mw = (wid & 3) * 32, nw = (wid >> 2) * 64;
    const int q = lane >> 3, rl = lane & 7;
    const unsigned aoff = (mw + rl + (q & 1) * 8) * APAD_B + (q >> 1) * 16;
    const unsigned boff = 2 * ATILE_B + (nw + rl + (q & 1) * 8) * APAD_B + (q >> 1) * 16;

    int st = 0;
    for (int t = 0; t < nst; ++t) {
        if (t + 1 < nst) asm volatile("cp.async.wait_group 1;");
        else             asm volatile("cp.async.wait_group 0;");
        __syncthreads();
        if (t + 2 < nst) {
            int s2 = st + 2; if (s2 >= NSTG) s2 -= NSTG;
            TISSUE(t + 2, s2);
        }
        const unsigned sa = sb + st * STG_B + aoff;
        const unsigned sB2 = sb + st * STG_B + boff;

        unsigned a[2][2][4];
#pragma unroll
        for (int p = 0; p < 2; p++)
#pragma unroll
            for (int mi = 0; mi < 2; mi++)
                LDSM4(a[p][mi], sa + p * ATILE_B + mi * 16 * APAD_B);

#pragma unroll
        for (int ng = 0; ng < 4; ng++) {
            unsigned bf[2][4];
#pragma unroll
            for (int p = 0; p < 2; p++)
                LDSM4(bf[p], sB2 + p * ATILE_B + ng * 16 * APAD_B);
#pragma unroll
            for (int mi = 0; mi < 2; mi++)
#pragma unroll
                for (int j = 0; j < 2; j++) {
                    float* dm = cm[mi][ng * 2 + j];
                    float* dc = cc[mi][ng * 2 + j];
                    MMA(dm, a[0][mi], bf[0][j], bf[0][j + 2]);
                    MMA(dc, a[0][mi], bf[1][j], bf[1][j + 2]);
                    MMA(dc, a[1][mi], bf[0][j], bf[0][j + 2]);
                }
        }
        __syncthreads();
        if (++st == NSTG) st = 0;
    }
#undef TISSUE

    /* epilogue: c-frag (mi): rows g/g+8, cols tg*2, tg*2+1 */
    const int g = lane >> 2, tg = lane & 3;
#pragma unroll
    for (int mi = 0; mi < 2; mi++) {
        const int r0 = m0 + mw + mi * 16 + g;
        const int r1 = r0 + 8;
        const float rs0 = rowscale ? rowscale[r0] : 1.f;
        const float rs1 = rowscale ? rowscale[r1] : 1.f;
#pragma unroll
        for (int nf = 0; nf < 8; nf++) {
            const int col = n0 + nw + nf * 8 + tg * 2;
            float o0 = cm[mi][nf][0] + cc[mi][nf][0];
            float o1 = cm[mi][nf][1] + cc[mi][nf][1];
            float o2 = cm[mi][nf][2] + cc[mi][nf][2];
            float o3 = cm[mi][nf][3] + cc[mi][nf][3];
            if (bias) {
                float bv0 = bias[col], bv1 = bias[col + 1];
                o0 += bv0; o1 += bv1; o2 += bv0; o3 += bv1;
            }
            if (relu) {
                o0 = fmaxf(o0, 0.f); o1 = fmaxf(o1, 0.f);
                o2 = fmaxf(o2, 0.f); o3 = fmaxf(o3, 0.f);
            }
            o0 *= rs0; o1 *= rs0; o2 *= rs1; o3 *= rs1;
            if (addend) {
                o0 += addend[(long long)r0 * ldadd + col];
                o1 += addend[(long long)r0 * ldadd + col + 1];
                o2 += addend[(long long)r1 * ldadd + col];
                o3 += addend[(long long)r1 * ldadd + col + 1];
            }
            *(float2*)(C + (long long)r0 * ldc + col) = make_float2(o0, o1);
            *(float2*)(C + (long long)r1 * ldc + col) = make_float2(o2, o3);
        }
    }
}

/* ------------- fp32 -> 2 bf16 planes ------------------------------------ */
__device__ __forceinline__ void split2(float v, __nv_bfloat16& b0, __nv_bfloat16& b1) {
    b0 = __float2bfloat16(v);
    b1 = __float2bfloat16(v - __bfloat162float(b0));
}
__global__ void split_rm(const float* __restrict__ in, __nv_bfloat16* __restrict__ out,
                         long long n, long long PS)
{
    long long i = (long long)blockIdx.x * blockDim.x + threadIdx.x;
    if (i >= n) return;
    __nv_bfloat16 b0, b1;
    split2(in[i], b0, b1);
    out[i] = b0; out[PS + i] = b1;
}
/* transpose + split: in [z][R][C] fp32 -> planes [z][C][R] bf16 */
__global__ void split_tr(const float* __restrict__ in, __nv_bfloat16* __restrict__ out,
                         int R, int C, long long PS)
{
    __shared__ float t[32][33];
    const long long zo = (long long)blockIdx.z * R * C;
    const float* ip = in + zo;
    __nv_bfloat16* op = out + zo;
    int x = blockIdx.x * 32 + threadIdx.x;
    int y0 = blockIdx.y * 32 + threadIdx.y;
#pragma unroll
    for (int j = 0; j < 32; j += 8)
        t[threadIdx.y + j][threadIdx.x] = ip[(long long)(y0 + j) * C + x];
    __syncthreads();
    int xo = blockIdx.y * 32 + threadIdx.x;
    int yo = blockIdx.x * 32 + threadIdx.y;
#pragma unroll
    for (int j = 0; j < 32; j += 8) {
        __nv_bfloat16 b0, b1;
        split2(t[threadIdx.x][threadIdx.y + j], b0, b1);
        long long oi = (long long)(yo + j) * R + xo;
        op[oi] = b0; op[PS + oi] = b1;
    }
}

/* ------------- colnorm --------------------------------------------------- */
__global__ void colnorm_kernel(const float* __restrict__ A, float* __restrict__ inv)
{
    int g = blockIdx.x * blockDim.x + threadIdx.x;
    int b = g >> 8, m = g & 255;
    const float* base = A + (long long)b * 65536 + m;
    float s = 0.f;
#pragma unroll 8
    for (int n = 0; n < 256; n++) s += fabsf(base[n * 256]);
    inv[g] = 1.f / fmaxf(s, 1e-12f);
}

/* ------------- masked Sinkhorn ------------------------------------------- */
__global__ __launch_bounds__(1024) void sinkhorn_kernel(
    float* __restrict__ buf, float* __restrict__ out,
    const int* __restrict__ n1, const int* __restrict__ iters_ptr)
{
    __shared__ float red[4 * 256];
    __shared__ float lsebuf[256];
    const int b = blockIdx.x;
    float* Mb = buf + (long long)b * 65536;
    const int nv = n1[b];
    const int iters = *iters_ptr;
    const int tid = threadIdx.x;
    const int warp = tid >> 5, lane = tid & 31;

    for (int idx = tid; idx < 65536; idx += 1024) {
        int r = idx >> 8;
        float v = Mb[idx];
        Mb[idx] = (r < nv) ? v / 0.05f : NEGV;
    }
    __syncthreads();
    for (int it = 0; it < iters; ++it) {
        if ((it & 1) == 0) {
            for (int r = warp; r < 256; r += 32) {
                float* rp = Mb + (r << 8);
                float v[8];
#pragma unroll
                for (int j = 0; j < 8; j++) v[j] = rp[lane + (j << 5)];
                float mx = v[0];
#pragma unroll
                for (int j = 1; j < 8; j++) mx = fmaxf(mx, v[j]);
#pragma unroll
                for (int o = 16; o > 0; o >>= 1)
                    mx = fmaxf(mx, __shfl_xor_sync(0xffffffffu, mx, o));
                float sm = 0.f;
#pragma unroll
                for (int j = 0; j < 8; j++) sm += expf(v[j] - mx);
#pragma unroll
                for (int o = 16; o > 0; o >>= 1)
                    sm += __shfl_xor_sync(0xffffffffu, sm, o);
                float lse = mx + logf(sm);
                bool ok = r < nv;
#pragma unroll
                for (int j = 0; j < 8; j++)
                    rp[lane + (j << 5)] = ok ? (v[j] - lse) : NEGV;
            }
            __syncthreads();
        } else {
            const int c = tid & 255, g = tid >> 8;
            float pm = NEGV;
            for (int r = g; r < 256; r += 4) pm = fmaxf(pm, Mb[(r << 8) + c]);
            red[(g << 8) + c] = pm;
            __syncthreads();
            if (tid < 256)
                lsebuf[tid] = fmaxf(fmaxf(red[tid], red[256 + tid]),
                                    fmaxf(red[512 + tid], red[768 + tid]));
            __syncthreads();
            float cm = lsebuf[c];
            float ps = 0.f;
            for (int r = g; r < 256; r += 4) ps += expf(Mb[(r << 8) + c] - cm);
            red[(g << 8) + c] = ps;
            __syncthreads();
            if (tid < 256)
                lsebuf[tid] = lsebuf[tid] + logf(red[tid] + red[256 + tid] +
                                                 red[512 + tid] + red[768 + tid]);
            __syncthreads();
            for (int idx = tid; idx < 65536; idx += 1024) {
                int r = idx >> 8, cc2 = idx & 255;
                Mb[idx] = (r < nv) ? (Mb[idx] - lsebuf[cc2]) : NEGV;
            }
            __syncthreads();
        }
    }
    float* ob = out + (long long)b * 65536;
    for (int idx = tid; idx < 65536; idx += 1024)
        ob[idx] = expf(Mb[idx]);
}

/* ------------- orchestration -------------------------------------------- */
extern "C" void kernel_launch(void* const* d_in, const int* in_sizes, int n_in,
                              void* d_out, int out_size)
{
    (void)in_sizes; (void)n_in; (void)out_size;
    const float* feat1 = (const float*)d_in[0];
    const float* feat2 = (const float*)d_in[1];
    const float* A1p   = (const float*)d_in[2];
    const float* A2p   = (const float*)d_in[3];
    const int*   n1p   = (const int*)d_in[4];
    const int*   skp   = (const int*)d_in[7];
    const float* W0a = (const float*)d_in[8],  *b0a = (const float*)d_in[9];
    const float* W0u = (const float*)d_in[10], *b0u = (const float*)d_in[11];
    const float* W1a = (const float*)d_in[12], *b1a = (const float*)d_in[13];
    const float* W1u = (const float*)d_in[14], *b1u = (const float*)d_in[15];
    const float* Wc  = (const float*)d_in[16], *bc  = (const float*)d_in[17];
    const float* Aaff0 = (const float*)d_in[18];
    const float* Aaff1 = (const float*)d_in[19];
    float* outp = (float*)d_out;

    __nv_bfloat16 *bfA, *bfB, *bfB2;
    float *ax, *ux, *e1, *e2, *tb, *m1, *m2, *sb, *col;
    cudaGetSymbolAddress((void**)&bfA,  g_bfA);
    cudaGetSymbolAddress((void**)&bfB,  g_bfB);
    cudaGetSymbolAddress((void**)&bfB2, g_bfB2);
    cudaGetSymbolAddress((void**)&ax,  g_ax);
    cudaGetSymbolAddress((void**)&ux,  g_ux);
    cudaGetSymbolAddress((void**)&e1,  g_e1);
    cudaGetSymbolAddress((void**)&e2,  g_e2);
    cudaGetSymbolAddress((void**)&tb,  g_tb);
    cudaGetSymbolAddress((void**)&m1,  g_m1);
    cudaGetSymbolAddress((void**)&m2,  g_m2);
    cudaGetSymbolAddress((void**)&sb,  g_sb);
    cudaGetSymbolAddress((void**)&col, g_col);

    cudaFuncSetAttribute(tgemm, cudaFuncAttributeMaxDynamicSharedMemorySize, SMEMT);

    const dim3 T32(32, 8);
    const long long SE = 524288;            /* 256*2048 per-batch */
    const long long SS = 65536;

    colnorm_kernel<<<32, 256>>>(A1p, col);
    colnorm_kernel<<<32, 256>>>(A2p, col + ROWS);

    /* gconv layer 0 : graph g = 1,2 */
    for (int g = 0; g < 2; g++) {
        const float* feat = g ? feat2 : feat1;
        const float* Ap   = g ? A2p : A1p;
        float* ev         = g ? e2 : e1;
        const float* cv   = col + g * ROWS;
        split_rm<<<32768, 256>>>(feat, bfA, 8192LL * 1024, PFEAT);
        split_tr<<<dim3(64, 32, 1), T32>>>(W0a, bfB, 1024, 2048, PW0);
        tgemm<<<dim3(64, 16, 1), 256, SMEMT>>>(8192, 2048, 1024, bfA, 1024, PFEAT, 0,
            bfB, 1024, PW0, 0, ax, 2048, 0, b0a, 1, cv, 0, 0, 0);
        split_tr<<<dim3(64, 32, 1), T32>>>(W0u, bfB, 1024, 2048, PW0);
        tgemm<<<dim3(64, 16, 1), 256, SMEMT>>>(8192, 2048, 1024, bfA, 1024, PFEAT, 0,
            bfB, 1024, PW0, 0, ux, 2048, 0, b0u, 1, 0, 0, 0, 0);
        split_rm<<<8192, 256>>>(Ap, bfA, 2097152LL, PADJ);
        split_tr<<<dim3(64, 8, 32), T32>>>(ax, bfB2, 256, 2048, PBIG);
        tgemm<<<dim3(2, 16, 32), 256, SMEMT>>>(256, 2048, 256, bfA, 256, PADJ, SS,
            bfB2, 256, PBIG, SE, ev, 2048, SE, 0, 0, 0, ux, 2048, SE);
    }

    /* affinity 0 + sinkhorn */
    split_rm<<<65536, 256>>>(e1, bfA, (long long)ROWS * CH, PBIG);
    split_tr<<<dim3(64, 64, 1), T32>>>(Aaff0, bfB, 2048, 2048, PAAF);
    tgemm<<<dim3(64, 16, 1), 256, SMEMT>>>(8192, 2048, 2048, bfA, 2048, PBIG, 0,
        bfB, 2048, PAAF, 0, tb, 2048, 0, 0, 0, 0, 0, 0, 0);
    split_rm<<<65536, 256>>>(tb, bfA, (long long)ROWS * CH, PBIG);
    split_rm<<<65536, 256>>>(e2, bfB, (long long)ROWS * CH, PBIG);
    tgemm<<<dim3(2, 2, 32), 256, SMEMT>>>(256, 256, 2048, bfA, 2048, PBIG, SE,
        bfB, 2048, PBIG, SE, sb, 256, SS, 0, 0, 0, 0, 0, 0);
    sinkhorn_kernel<<<32, 1024>>>(sb, sb, n1p, skp);

    /* cross update: m1 = e1@WcT + (s@e2)@WcB + bc ; m2 = e2@WcT + (sT@e1)@WcB + bc */
    split_rm<<<8192, 256>>>(sb, bfA, 2097152LL, PSB);
    split_tr<<<dim3(64, 8, 32), T32>>>(e2, bfB2, 256, 2048, PBIG);
    tgemm<<<dim3(2, 16, 32), 256, SMEMT>>>(256, 2048, 256, bfA, 256, PSB, SS,
        bfB2, 256, PBIG, SE, tb, 2048, SE, 0, 0, 0, 0, 0, 0);     /* u -> tb */
    split_tr<<<dim3(64, 128, 1), T32>>>(Wc, bfB, 4096, 2048, PWC);
    split_rm<<<65536, 256>>>(e1, bfA, (long long)ROWS * CH, PBIG);
    tgemm<<<dim3(64, 16, 1), 256, SMEMT>>>(8192, 2048, 2048, bfA, 2048, PBIG, 0,
        bfB, 4096, PWC, 0, m1, 2048, 0, bc, 0, 0, 0, 0, 0);
    split_rm<<<65536, 256>>>(tb, bfA, (long long)ROWS * CH, PBIG);
    tgemm<<<dim3(64, 16, 1), 256, SMEMT>>>(8192, 2048, 2048, bfA, 2048, PBIG, 0,
        bfB + 2048, 4096, PWC, 0, m1, 2048, 0, 0, 0, 0, m1, 2048, 0);
    split_tr<<<dim3(8, 8, 32), T32>>>(sb, bfA, 256, 256, PSB);    /* sT planes */
    split_tr<<<dim3(64, 8, 32), T32>>>(e1, bfB2, 256, 2048, PBIG);
    tgemm<<<dim3(2, 16, 32), 256, SMEMT>>>(256, 2048, 256, bfA, 256, PSB, SS,
        bfB2, 256, PBIG, SE, ax, 2048, SE, 0, 0, 0, 0, 0, 0);     /* v -> ax */
    split_rm<<<65536, 256>>>(e2, bfA, (long long)ROWS * CH, PBIG);
    tgemm<<<dim3(64, 16, 1), 256, SMEMT>>>(8192, 2048, 2048, bfA, 2048, PBIG, 0,
        bfB, 4096, PWC, 0, m2, 2048, 0, bc, 0, 0, 0, 0, 0);
    split_rm<<<65536, 256>>>(ax, bfA, (long long)ROWS * CH, PBIG);
    tgemm<<<dim3(64, 16, 1), 256, SMEMT>>>(8192, 2048, 2048, bfA, 2048, PBIG, 0,
        bfB + 2048, 4096, PWC, 0, m2, 2048, 0, 0, 0, 0, m2, 2048, 0);

    /* gconv layer 1 */
    for (int g = 0; g < 2; g++) {
        const float* mv = g ? m2 : m1;
        const float* Ap = g ? A2p : A1p;
        float* ev       = g ? e2 : e1;
        const float* cv = col + g * ROWS;
        split_rm<<<65536, 256>>>(mv, bfA, (long long)ROWS * CH, PBIG);
        split_tr<<<dim3(64, 64, 1), T32>>>(W1a, bfB, 2048, 2048, PAAF);
        tgemm<<<dim3(64, 16, 1), 256, SMEMT>>>(8192, 2048, 2048, bfA, 2048, PBIG, 0,
            bfB, 2048, PAAF, 0, ax, 2048, 0, b1a, 1, cv, 0, 0, 0);
        split_tr<<<dim3(64, 64, 1), T32>>>(W1u, bfB, 2048, 2048, PAAF);
        tgemm<<<dim3(64, 16, 1), 256, SMEMT>>>(8192, 2048, 2048, bfA, 2048, PBIG, 0,
            bfB, 2048, PAAF, 0, ux, 2048, 0, b1u, 1, 0, 0, 0, 0);
        split_rm<<<8192, 256>>>(Ap, bfA, 2097152LL, PADJ);
        split_tr<<<dim3(64, 8, 32), T32>>>(ax, bfB2, 256, 2048, PBIG);
        tgemm<<<dim3(2, 16, 32), 256, SMEMT>>>(256, 2048, 256, bfA, 256, PADJ, SS,
            bfB2, 256, PBIG, SE, ev, 2048, SE, 0, 0, 0, ux, 2048, SE);
    }

    /* affinity 1 + final sinkhorn */
    split_rm<<<65536, 256>>>(e1, bfA, (long long)ROWS * CH, PBIG);
    split_tr<<<dim3(64, 64, 1), T32>>>(Aaff1, bfB, 2048, 2048, PAAF);
    tgemm<<<dim3(64, 16, 1), 256, SMEMT>>>(8192, 2048, 2048, bfA, 2048, PBIG, 0,
        bfB, 2048, PAAF, 0, tb, 2048, 0, 0, 0, 0, 0, 0, 0);
    split_rm<<<65536, 256>>>(tb, bfA, (long long)ROWS * CH, PBIG);
    split_rm<<<65536, 256>>>(e2, bfB, (long long)ROWS * CH, PBIG);
    tgemm<<<dim3(2, 2, 32), 256, SMEMT>>>(256, 256, 2048, bfA, 2048, PBIG, SE,
        bfB, 2048, PBIG, SE, sb, 256, SS, 0, 0, 0, 0, 0, 0);
    sinkhorn_kernel<<<32, 1024>>>(sb, outp, n1p, skp);
}